// round 4
// baseline (speedup 1.0000x reference)
#include <cuda_runtime.h>
#include <math.h>

#define BATCH 4
#define SEQ   4096
#define EMB   512

// Scratch (__device__ globals: sanctioned, no runtime allocation)
__device__ float g_q [BATCH * SEQ * EMB];                 // 32 MB  [b*s][e]
__device__ float g_k [BATCH * SEQ * EMB];                 // 32 MB  [b*s][e]
__device__ float g_vt[BATCH * SEQ * EMB];                 // 32 MB  [b][e][s] (transposed)
__device__ float g_s [(size_t)BATCH * SEQ * SEQ];         // 256 MB scores/attn

__device__ __forceinline__ float cvt_tf32(float x) {
    asm("cvt.rna.tf32.f32 %0, %0;" : "+f"(x));
    return x;
}

#define TILE_F  4608          // 128 * 36 floats per tile
#define STAGES  3
#define SMEM_BYTES (STAGES * 2 * TILE_F * 4)   // 110592

__device__ __forceinline__ void cp16(unsigned dst, const float* src) {
    asm volatile("cp.async.cg.shared.global [%0], [%1], 16;" :: "r"(dst), "l"(src));
}

// ---------------------------------------------------------------------------
// TF32(x2) tensor-core NT GEMM:  C[m,n] = sum_k A[m,k]*B[n,k] (+bias[n])
// Block tile 128x128, BK=32, 512 threads (16 warps, 4m x 4n), warp tile 32x32.
// Raw fp32 tiles in smem via cp.async 3-stage ring; hi/lo split in registers
// after ldmatrix; 3 mma (hh + hl + lh) per fragment pair.
// TRANSC: scatter C transposed into [b][n][s] layout (V projection).
// ---------------------------------------------------------------------------
template <bool BIAS, bool TRANSC>
__global__ void __launch_bounds__(512)
mma_gemm_nt(const float* __restrict__ A, const float* __restrict__ B,
            const float* __restrict__ bias, float* __restrict__ C,
            int K, int lda, int ldb, int ldc,
            long sA, long sB, long sC)
{
    extern __shared__ float smem[];

    const int bz = blockIdx.z;
    A += (long)bz * sA;
    B += (long)bz * sB;
    C += (long)bz * sC;

    const int tid  = threadIdx.x;
    const int lane = tid & 31;
    const int wid  = tid >> 5;
    const int wm   = (wid & 3) * 32;
    const int wn   = (wid >> 2) * 32;
    const int m0   = blockIdx.y * 128;
    const int n0   = blockIdx.x * 128;

    const unsigned smemU = (unsigned)__cvta_generic_to_shared(smem);

    // cp.async load mapping: 512 threads x 2 chunks cover 128x32 tile (1024 x 16B)
    const int r0c = tid >> 3;            // chunk0 row 0..63
    const int r1c = r0c + 64;            // chunk1 row
    const int k4  = (tid & 7) * 4;       // 0..28

    float acc[2][4][4];
#pragma unroll
    for (int i = 0; i < 2; i++)
#pragma unroll
        for (int j = 0; j < 4; j++)
#pragma unroll
            for (int r = 0; r < 4; r++) acc[i][j][r] = 0.f;

    // ldmatrix lane addressing (validated mapping from round 2/3)
    const int r8 = lane & 7;
    const int hb = (lane >> 3) & 1;
    const int hf = lane >> 4;
    unsigned aOff[2], bOff[2];
#pragma unroll
    for (int mi = 0; mi < 2; mi++)
        aOff[mi] = ((wm + mi * 16 + r8 + hb * 8) * 36 + hf * 4) << 2;
#pragma unroll
    for (int p = 0; p < 2; p++)
        bOff[p] = ((wn + p * 16 + r8 + hf * 8) * 36 + hb * 4) << 2;

    const int niter = K >> 5;

    // ---- prologue: stage 0 and 1 ----
#pragma unroll
    for (int kt = 0; kt < 2; kt++) {
        unsigned aB = smemU + (unsigned)(kt * 2 * TILE_F) * 4u;
        unsigned bB = aB + TILE_F * 4u;
        cp16(aB + (r0c * 36 + k4) * 4, A + (long)(m0 + r0c) * lda + kt * 32 + k4);
        cp16(aB + (r1c * 36 + k4) * 4, A + (long)(m0 + r1c) * lda + kt * 32 + k4);
        cp16(bB + (r0c * 36 + k4) * 4, B + (long)(n0 + r0c) * ldb + kt * 32 + k4);
        cp16(bB + (r1c * 36 + k4) * 4, B + (long)(n0 + r1c) * ldb + kt * 32 + k4);
        asm volatile("cp.async.commit_group;");
    }

    for (int it = 0; it < niter; it++) {
        if (it < niter - 1)
            asm volatile("cp.async.wait_group 1;");
        else
            asm volatile("cp.async.wait_group 0;");
        __syncthreads();

        // issue stage it+2 into the slot consumed at it-1
        if (it + 2 < niter) {
            const int kt = it + 2;
            const int s  = kt % STAGES;
            unsigned aB = smemU + (unsigned)(s * 2 * TILE_F) * 4u;
            unsigned bB = aB + TILE_F * 4u;
            cp16(aB + (r0c * 36 + k4) * 4, A + (long)(m0 + r0c) * lda + kt * 32 + k4);
            cp16(aB + (r1c * 36 + k4) * 4, A + (long)(m0 + r1c) * lda + kt * 32 + k4);
            cp16(bB + (r0c * 36 + k4) * 4, B + (long)(n0 + r0c) * ldb + kt * 32 + k4);
            cp16(bB + (r1c * 36 + k4) * 4, B + (long)(n0 + r1c) * ldb + kt * 32 + k4);
            asm volatile("cp.async.commit_group;");
        }

        const unsigned asB = smemU + (unsigned)((it % STAGES) * 2 * TILE_F) * 4u;
        const unsigned bsB = asB + TILE_F * 4u;

#pragma unroll
        for (int ks = 0; ks < 4; ks++) {
            // A fragments: load raw fp32, split hi/lo in registers
            unsigned aFh[2][4], aFl[2][4];
#pragma unroll
            for (int mi = 0; mi < 2; mi++) {
                unsigned q0, q1, q2, q3;
                asm volatile(
                    "ldmatrix.sync.aligned.m8n8.x4.shared.b16 {%0,%1,%2,%3}, [%4];"
                    : "=r"(q0), "=r"(q1), "=r"(q2), "=r"(q3)
                    : "r"(asB + aOff[mi] + ks * 32));
                float x0 = __uint_as_float(q0), x1 = __uint_as_float(q1);
                float x2 = __uint_as_float(q2), x3 = __uint_as_float(q3);
                float h0 = cvt_tf32(x0), h1 = cvt_tf32(x1);
                float h2 = cvt_tf32(x2), h3 = cvt_tf32(x3);
                aFh[mi][0] = __float_as_uint(h0); aFh[mi][1] = __float_as_uint(h1);
                aFh[mi][2] = __float_as_uint(h2); aFh[mi][3] = __float_as_uint(h3);
                aFl[mi][0] = __float_as_uint(cvt_tf32(x0 - h0));
                aFl[mi][1] = __float_as_uint(cvt_tf32(x1 - h1));
                aFl[mi][2] = __float_as_uint(cvt_tf32(x2 - h2));
                aFl[mi][3] = __float_as_uint(cvt_tf32(x3 - h3));
            }

#pragma unroll
            for (int p = 0; p < 2; p++) {
                unsigned q0, q1, q2, q3;
                asm volatile(
                    "ldmatrix.sync.aligned.m8n8.x4.shared.b16 {%0,%1,%2,%3}, [%4];"
                    : "=r"(q0), "=r"(q1), "=r"(q2), "=r"(q3)
                    : "r"(bsB + bOff[p] + ks * 32));
                float x0 = __uint_as_float(q0), x1 = __uint_as_float(q1);
                float x2 = __uint_as_float(q2), x3 = __uint_as_float(q3);
                float h0 = cvt_tf32(x0), h1 = cvt_tf32(x1);
                float h2 = cvt_tf32(x2), h3 = cvt_tf32(x3);
                unsigned bFh[2][2], bFl[2][2];
                bFh[0][0] = __float_as_uint(h0); bFh[0][1] = __float_as_uint(h1);
                bFh[1][0] = __float_as_uint(h2); bFh[1][1] = __float_as_uint(h3);
                bFl[0][0] = __float_as_uint(cvt_tf32(x0 - h0));
                bFl[0][1] = __float_as_uint(cvt_tf32(x1 - h1));
                bFl[1][0] = __float_as_uint(cvt_tf32(x2 - h2));
                bFl[1][1] = __float_as_uint(cvt_tf32(x3 - h3));

#define MMA(aa, bb, mi, jj, nj)                                               \
    asm volatile(                                                             \
        "mma.sync.aligned.m16n8k8.row.col.f32.tf32.tf32.f32 "                 \
        "{%0,%1,%2,%3}, {%4,%5,%6,%7}, {%8,%9}, {%0,%1,%2,%3};"               \
        : "+f"(acc[mi][nj][0]), "+f"(acc[mi][nj][1]),                         \
          "+f"(acc[mi][nj][2]), "+f"(acc[mi][nj][3])                          \
        : "r"(aa[mi][0]), "r"(aa[mi][1]), "r"(aa[mi][2]), "r"(aa[mi][3]),     \
          "r"(bb[jj][0]), "r"(bb[jj][1]))

#pragma unroll
                for (int mi = 0; mi < 2; mi++)
#pragma unroll
                    for (int jj = 0; jj < 2; jj++) {
                        const int nj = p * 2 + jj;
                        MMA(aFh, bFl, mi, jj, nj);   // hi*lo
                        MMA(aFl, bFh, mi, jj, nj);   // lo*hi
                        MMA(aFh, bFh, mi, jj, nj);   // hi*hi
                    }
#undef MMA
            }
        }
        __syncthreads();
    }

    // epilogue
    const int g = lane >> 2;
    const int t = lane & 3;
#pragma unroll
    for (int nj = 0; nj < 4; nj++) {
        const int col = n0 + wn + nj * 8 + t * 2;
        float b0 = 0.f, b1 = 0.f;
        if (BIAS) { b0 = bias[col]; b1 = bias[col + 1]; }
#pragma unroll
        for (int mi = 0; mi < 2; mi++) {
            const int row = m0 + wm + mi * 16 + g;
            float c0 = acc[mi][nj][0] + b0;
            float c1 = acc[mi][nj][1] + b1;
            float c2 = acc[mi][nj][2] + b0;
            float c3 = acc[mi][nj][3] + b1;
            if (!TRANSC) {
                *reinterpret_cast<float2*>(&C[(long)row * ldc + col]) = make_float2(c0, c1);
                *reinterpret_cast<float2*>(&C[(long)(row + 8) * ldc + col]) = make_float2(c2, c3);
            } else {
                const int bb = row >> 12;
                const int s  = row & 4095;
                float* Cb = C + (long)bb * EMB * SEQ + s;
                Cb[(long)col * SEQ]           = c0;
                Cb[(long)(col + 1) * SEQ]     = c1;
                Cb[(long)col * SEQ + 8]       = c2;
                Cb[(long)(col + 1) * SEQ + 8] = c3;
            }
        }
    }
}

// ---------------------------------------------------------------------------
// Row softmax, in place. One block per 4096-col row, 256 threads.
// ---------------------------------------------------------------------------
__global__ void __launch_bounds__(256)
softmax_rows(float* __restrict__ S)
{
    const long row = blockIdx.x;
    float* p = S + row * (long)SEQ;
    const int tid  = threadIdx.x;
    const int lane = tid & 31;
    const int wid  = tid >> 5;

    float vals[16];
    float m = -3.0e38f;
#pragma unroll
    for (int i = 0; i < 4; i++) {
        float4 v = reinterpret_cast<float4*>(p)[tid + i * 256];
        vals[i * 4 + 0] = v.x; vals[i * 4 + 1] = v.y;
        vals[i * 4 + 2] = v.z; vals[i * 4 + 3] = v.w;
        m = fmaxf(m, fmaxf(fmaxf(v.x, v.y), fmaxf(v.z, v.w)));
    }

    __shared__ float red[8];
#pragma unroll
    for (int off = 16; off > 0; off >>= 1)
        m = fmaxf(m, __shfl_xor_sync(0xffffffffu, m, off));
    if (lane == 0) red[wid] = m;
    __syncthreads();
    float mAll = red[0];
#pragma unroll
    for (int w = 1; w < 8; w++) mAll = fmaxf(mAll, red[w]);
    __syncthreads();

    float s = 0.f;
#pragma unroll
    for (int i = 0; i < 16; i++) {
        vals[i] = __expf(vals[i] - mAll);
        s += vals[i];
    }
#pragma unroll
    for (int off = 16; off > 0; off >>= 1)
        s += __shfl_xor_sync(0xffffffffu, s, off);
    if (lane == 0) red[wid] = s;
    __syncthreads();
    float sAll = 0.f;
#pragma unroll
    for (int w = 0; w < 8; w++) sAll += red[w];
    const float inv = 1.0f / sAll;

#pragma unroll
    for (int i = 0; i < 4; i++) {
        float4 v;
        v.x = vals[i * 4 + 0] * inv; v.y = vals[i * 4 + 1] * inv;
        v.z = vals[i * 4 + 2] * inv; v.w = vals[i * 4 + 3] * inv;
        reinterpret_cast<float4*>(p)[tid + i * 256] = v;
    }
}

// ---------------------------------------------------------------------------
extern "C" void kernel_launch(void* const* d_in, const int* in_sizes, int n_in,
                              void* d_out, int out_size)
{
    const float* q_in = (const float*)d_in[0];
    const float* k_in = (const float*)d_in[1];
    const float* v_in = (const float*)d_in[2];
    const float* Wq   = (const float*)d_in[3];
    const float* bq   = (const float*)d_in[4];
    const float* Wk   = (const float*)d_in[5];
    const float* bk   = (const float*)d_in[6];
    const float* Wv   = (const float*)d_in[7];
    const float* bv   = (const float*)d_in[8];
    float* out = (float*)d_out;

    float *gq, *gk, *gvt, *gs;
    cudaGetSymbolAddress((void**)&gq,  g_q);
    cudaGetSymbolAddress((void**)&gk,  g_k);
    cudaGetSymbolAddress((void**)&gvt, g_vt);
    cudaGetSymbolAddress((void**)&gs,  g_s);

    static bool attrDone = false;
    if (!attrDone) {
        cudaFuncSetAttribute(mma_gemm_nt<true,  false>,
                             cudaFuncAttributeMaxDynamicSharedMemorySize, SMEM_BYTES);
        cudaFuncSetAttribute(mma_gemm_nt<true,  true>,
                             cudaFuncAttributeMaxDynamicSharedMemorySize, SMEM_BYTES);
        cudaFuncSetAttribute(mma_gemm_nt<false, false>,
                             cudaFuncAttributeMaxDynamicSharedMemorySize, SMEM_BYTES);
        attrDone = true;
    }

    dim3 blk(512);

    // 1) projections: [16384,512] @ W^T + b   (V transposed into g_vt)
    {
        dim3 grd(EMB / 128, (BATCH * SEQ) / 128, 1);
        mma_gemm_nt<true, false><<<grd, blk, SMEM_BYTES>>>(
            q_in, Wq, bq, gq, EMB, EMB, EMB, EMB, 0, 0, 0);
        mma_gemm_nt<true, false><<<grd, blk, SMEM_BYTES>>>(
            k_in, Wk, bk, gk, EMB, EMB, EMB, EMB, 0, 0, 0);
        mma_gemm_nt<true, true><<<grd, blk, SMEM_BYTES>>>(
            v_in, Wv, bv, gvt, EMB, EMB, EMB, SEQ, 0, 0, 0);
    }

    // 2) scores[b] = q[b] @ k[b]^T
    {
        dim3 grd(SEQ / 128, SEQ / 128, BATCH);
        mma_gemm_nt<false, false><<<grd, blk, SMEM_BYTES>>>(
            gq, gk, nullptr, gs, EMB, EMB, EMB, SEQ,
            (long)SEQ * EMB, (long)SEQ * EMB, (long)SEQ * SEQ);
    }

    // 3) row softmax in place
    softmax_rows<<<BATCH * SEQ, 256>>>(gs);

    // 4) out[b] = attn[b] @ v[b]   (B = vT[b], NT form)
    {
        dim3 grd(EMB / 128, SEQ / 128, BATCH);
        mma_gemm_nt<false, false><<<grd, blk, SMEM_BYTES>>>(
            gs, gvt, nullptr, out, SEQ, SEQ, SEQ, EMB,
            (long)SEQ * SEQ, (long)EMB * SEQ, (long)SEQ * EMB);
    }
}

// round 5
// speedup vs baseline: 1.1723x; 1.1723x over previous
#include <cuda_runtime.h>
#include <math.h>

#define BATCH 4
#define SEQ   4096
#define EMB   512

// Scratch (__device__ globals: sanctioned, no runtime allocation)
__device__ float g_q [BATCH * SEQ * EMB];                 // 32 MB  [b*s][e]
__device__ float g_k [BATCH * SEQ * EMB];                 // 32 MB  [b*s][e]
__device__ float g_vt[BATCH * SEQ * EMB];                 // 32 MB  [b][e][s] (transposed)
__device__ float g_s [(size_t)BATCH * SEQ * SEQ];         // 256 MB scores/attn

__device__ __forceinline__ float cvt_tf32(float x) {
    asm("cvt.rna.tf32.f32 %0, %0;" : "+f"(x));
    return x;
}

#define TILE_F 4608                        // 128 * 36 floats per tile
#define STAGE_F (4 * TILE_F)               // AsH, BsH, AsL, BsL
#define SMEM_BYTES (2 * STAGE_F * 4)       // 147456 B (double buffer)

// ---------------------------------------------------------------------------
// TF32(x2) tensor-core NT GEMM:  C[m,n] = sum_k A[m,k]*B[n,k] (+bias[n])
// Block tile 128x128, BK=32, 512 threads (16 warps, 4m x 4n), warp tile 32x32.
// hi/lo split ONCE at staging time into smem (AsH/AsL/BsH/BsL), double
// buffered, one __syncthreads per iter. 3 mma (hh+hl+lh) per fragment pair.
// TRANSC: scatter C transposed into [b][n][s] layout (V projection).
// ---------------------------------------------------------------------------
template <bool BIAS, bool TRANSC>
__global__ void __launch_bounds__(512)
mma_gemm_nt(const float* __restrict__ A, const float* __restrict__ B,
            const float* __restrict__ bias, float* __restrict__ C,
            int K, int lda, int ldb, int ldc,
            long sA, long sB, long sC)
{
    extern __shared__ float smem[];

    const int bz = blockIdx.z;
    A += (long)bz * sA;
    B += (long)bz * sB;
    C += (long)bz * sC;

    const int tid  = threadIdx.x;
    const int lane = tid & 31;
    const int wid  = tid >> 5;
    const int wm   = (wid & 3) * 32;
    const int wn   = (wid >> 2) * 32;
    const int m0   = blockIdx.y * 128;
    const int n0   = blockIdx.x * 128;

    // load mapping: 512 threads x 2 float4 per 128x32 tile
    const int r0c = tid >> 3;            // rows 0..63
    const int r1c = r0c + 64;            // rows 64..127
    const int k4  = (tid & 7) * 4;       // 0..28
    const float* Ag0 = A + (long)(m0 + r0c) * lda + k4;
    const float* Ag1 = A + (long)(m0 + r1c) * lda + k4;
    const float* Bg0 = B + (long)(n0 + r0c) * ldb + k4;
    const float* Bg1 = B + (long)(n0 + r1c) * ldb + k4;

    float acc[2][4][4];
#pragma unroll
    for (int i = 0; i < 2; i++)
#pragma unroll
        for (int j = 0; j < 4; j++)
#pragma unroll
            for (int r = 0; r < 4; r++) acc[i][j][r] = 0.f;

    // ldmatrix lane addressing (validated in rounds 2-4)
    const unsigned smemU = (unsigned)__cvta_generic_to_shared(smem);
    const int r8 = lane & 7;
    const int hb = (lane >> 3) & 1;
    const int hf = lane >> 4;
    unsigned aOff[2], bOff[2];
#pragma unroll
    for (int mi = 0; mi < 2; mi++)
        aOff[mi] = ((wm + mi * 16 + r8 + hb * 8) * 36 + hf * 4) << 2;
#pragma unroll
    for (int p = 0; p < 2; p++)
        bOff[p] = ((wn + p * 16 + r8 + hf * 8) * 36 + hb * 4) << 2;

    const int niter = K >> 5;

    // staging store helper offsets (floats)
    const int s0 = r0c * 36 + k4;
    const int s1 = r1c * 36 + k4;

#define SPLIT_STORE(buf, va0, va1, vb0, vb1)                                   \
    do {                                                                       \
        float* AsH = smem + (buf) * STAGE_F;                                   \
        float* BsH = AsH + TILE_F;                                             \
        float* AsL = AsH + 2 * TILE_F;                                         \
        float* BsL = AsH + 3 * TILE_F;                                         \
        float4 h, l;                                                           \
        h = make_float4(cvt_tf32(va0.x), cvt_tf32(va0.y),                      \
                        cvt_tf32(va0.z), cvt_tf32(va0.w));                     \
        l = make_float4(cvt_tf32(va0.x - h.x), cvt_tf32(va0.y - h.y),          \
                        cvt_tf32(va0.z - h.z), cvt_tf32(va0.w - h.w));         \
        *reinterpret_cast<float4*>(&AsH[s0]) = h;                              \
        *reinterpret_cast<float4*>(&AsL[s0]) = l;                              \
        h = make_float4(cvt_tf32(va1.x), cvt_tf32(va1.y),                      \
                        cvt_tf32(va1.z), cvt_tf32(va1.w));                     \
        l = make_float4(cvt_tf32(va1.x - h.x), cvt_tf32(va1.y - h.y),          \
                        cvt_tf32(va1.z - h.z), cvt_tf32(va1.w - h.w));         \
        *reinterpret_cast<float4*>(&AsH[s1]) = h;                              \
        *reinterpret_cast<float4*>(&AsL[s1]) = l;                              \
        h = make_float4(cvt_tf32(vb0.x), cvt_tf32(vb0.y),                      \
                        cvt_tf32(vb0.z), cvt_tf32(vb0.w));                     \
        l = make_float4(cvt_tf32(vb0.x - h.x), cvt_tf32(vb0.y - h.y),          \
                        cvt_tf32(vb0.z - h.z), cvt_tf32(vb0.w - h.w));         \
        *reinterpret_cast<float4*>(&BsH[s0]) = h;                              \
        *reinterpret_cast<float4*>(&BsL[s0]) = l;                              \
        h = make_float4(cvt_tf32(vb1.x), cvt_tf32(vb1.y),                      \
                        cvt_tf32(vb1.z), cvt_tf32(vb1.w));                     \
        l = make_float4(cvt_tf32(vb1.x - h.x), cvt_tf32(vb1.y - h.y),          \
                        cvt_tf32(vb1.z - h.z), cvt_tf32(vb1.w - h.w));         \
        *reinterpret_cast<float4*>(&BsH[s1]) = h;                              \
        *reinterpret_cast<float4*>(&BsL[s1]) = l;                              \
    } while (0)

    // ---- prologue: tile 0 ----
    {
        float4 a0 = *reinterpret_cast<const float4*>(Ag0);
        float4 a1 = *reinterpret_cast<const float4*>(Ag1);
        float4 b0 = *reinterpret_cast<const float4*>(Bg0);
        float4 b1 = *reinterpret_cast<const float4*>(Bg1);
        SPLIT_STORE(0, a0, a1, b0, b1);
    }
    __syncthreads();

    for (int it = 0; it < niter; it++) {
        const int cur = it & 1;

        // prefetch tile it+1 into registers (overlaps with compute below)
        float4 pa0, pa1, pb0, pb1;
        const bool more = (it + 1 < niter);
        if (more) {
            const int ko = (it + 1) * 32;
            pa0 = *reinterpret_cast<const float4*>(Ag0 + ko);
            pa1 = *reinterpret_cast<const float4*>(Ag1 + ko);
            pb0 = *reinterpret_cast<const float4*>(Bg0 + ko);
            pb1 = *reinterpret_cast<const float4*>(Bg1 + ko);
        }

        const unsigned stB = smemU + (unsigned)(cur * STAGE_F) * 4u;
        const unsigned aH = stB;
        const unsigned bH = stB + TILE_F * 4u;
        const unsigned aL = stB + 2u * TILE_F * 4u;
        const unsigned bL = stB + 3u * TILE_F * 4u;

#pragma unroll
        for (int ks = 0; ks < 4; ks++) {
            unsigned aFh[2][4], aFl[2][4];
            unsigned bFh[4][2], bFl[4][2];
#pragma unroll
            for (int mi = 0; mi < 2; mi++) {
                asm volatile(
                    "ldmatrix.sync.aligned.m8n8.x4.shared.b16 {%0,%1,%2,%3}, [%4];"
                    : "=r"(aFh[mi][0]), "=r"(aFh[mi][1]), "=r"(aFh[mi][2]), "=r"(aFh[mi][3])
                    : "r"(aH + aOff[mi] + ks * 32));
                asm volatile(
                    "ldmatrix.sync.aligned.m8n8.x4.shared.b16 {%0,%1,%2,%3}, [%4];"
                    : "=r"(aFl[mi][0]), "=r"(aFl[mi][1]), "=r"(aFl[mi][2]), "=r"(aFl[mi][3])
                    : "r"(aL + aOff[mi] + ks * 32));
            }
#pragma unroll
            for (int p = 0; p < 2; p++) {
                unsigned q0, q1, q2, q3;
                asm volatile(
                    "ldmatrix.sync.aligned.m8n8.x4.shared.b16 {%0,%1,%2,%3}, [%4];"
                    : "=r"(q0), "=r"(q1), "=r"(q2), "=r"(q3)
                    : "r"(bH + bOff[p] + ks * 32));
                bFh[2 * p][0] = q0; bFh[2 * p][1] = q1;
                bFh[2 * p + 1][0] = q2; bFh[2 * p + 1][1] = q3;
                asm volatile(
                    "ldmatrix.sync.aligned.m8n8.x4.shared.b16 {%0,%1,%2,%3}, [%4];"
                    : "=r"(q0), "=r"(q1), "=r"(q2), "=r"(q3)
                    : "r"(bL + bOff[p] + ks * 32));
                bFl[2 * p][0] = q0; bFl[2 * p][1] = q1;
                bFl[2 * p + 1][0] = q2; bFl[2 * p + 1][1] = q3;
            }

#define MMA(aa, bb, mi, nj)                                                   \
    asm volatile(                                                             \
        "mma.sync.aligned.m16n8k8.row.col.f32.tf32.tf32.f32 "                 \
        "{%0,%1,%2,%3}, {%4,%5,%6,%7}, {%8,%9}, {%0,%1,%2,%3};"               \
        : "+f"(acc[mi][nj][0]), "+f"(acc[mi][nj][1]),                         \
          "+f"(acc[mi][nj][2]), "+f"(acc[mi][nj][3])                          \
        : "r"(aa[mi][0]), "r"(aa[mi][1]), "r"(aa[mi][2]), "r"(aa[mi][3]),     \
          "r"(bb[nj][0]), "r"(bb[nj][1]))

#pragma unroll
            for (int mi = 0; mi < 2; mi++)
#pragma unroll
                for (int nj = 0; nj < 4; nj++) {
                    MMA(aFh, bFl, mi, nj);   // hi*lo
                    MMA(aFl, bFh, mi, nj);   // lo*hi
                    MMA(aFh, bFh, mi, nj);   // hi*hi
                }
#undef MMA
        }

        // stage tile it+1 into the other buffer (no one reads it this iter)
        if (more)
            SPLIT_STORE(1 - cur, pa0, pa1, pb0, pb1);
        __syncthreads();
    }
#undef SPLIT_STORE

    // epilogue
    const int g = lane >> 2;
    const int t = lane & 3;
#pragma unroll
    for (int nj = 0; nj < 4; nj++) {
        const int col = n0 + wn + nj * 8 + t * 2;
        float b0 = 0.f, b1 = 0.f;
        if (BIAS) { b0 = bias[col]; b1 = bias[col + 1]; }
#pragma unroll
        for (int mi = 0; mi < 2; mi++) {
            const int row = m0 + wm + mi * 16 + g;
            float c0 = acc[mi][nj][0] + b0;
            float c1 = acc[mi][nj][1] + b1;
            float c2 = acc[mi][nj][2] + b0;
            float c3 = acc[mi][nj][3] + b1;
            if (!TRANSC) {
                *reinterpret_cast<float2*>(&C[(long)row * ldc + col]) = make_float2(c0, c1);
                *reinterpret_cast<float2*>(&C[(long)(row + 8) * ldc + col]) = make_float2(c2, c3);
            } else {
                const int bb = row >> 12;
                const int s  = row & 4095;
                float* Cb = C + (long)bb * EMB * SEQ + s;
                Cb[(long)col * SEQ]           = c0;
                Cb[(long)(col + 1) * SEQ]     = c1;
                Cb[(long)col * SEQ + 8]       = c2;
                Cb[(long)(col + 1) * SEQ + 8] = c3;
            }
        }
    }
}

// ---------------------------------------------------------------------------
// Row softmax, in place. One block per 4096-col row, 256 threads.
// ---------------------------------------------------------------------------
__global__ void __launch_bounds__(256)
softmax_rows(float* __restrict__ S)
{
    const long row = blockIdx.x;
    float* p = S + row * (long)SEQ;
    const int tid  = threadIdx.x;
    const int lane = tid & 31;
    const int wid  = tid >> 5;

    float vals[16];
    float m = -3.0e38f;
#pragma unroll
    for (int i = 0; i < 4; i++) {
        float4 v = reinterpret_cast<float4*>(p)[tid + i * 256];
        vals[i * 4 + 0] = v.x; vals[i * 4 + 1] = v.y;
        vals[i * 4 + 2] = v.z; vals[i * 4 + 3] = v.w;
        m = fmaxf(m, fmaxf(fmaxf(v.x, v.y), fmaxf(v.z, v.w)));
    }

    __shared__ float red[8];
#pragma unroll
    for (int off = 16; off > 0; off >>= 1)
        m = fmaxf(m, __shfl_xor_sync(0xffffffffu, m, off));
    if (lane == 0) red[wid] = m;
    __syncthreads();
    float mAll = red[0];
#pragma unroll
    for (int w = 1; w < 8; w++) mAll = fmaxf(mAll, red[w]);
    __syncthreads();

    float s = 0.f;
#pragma unroll
    for (int i = 0; i < 16; i++) {
        vals[i] = __expf(vals[i] - mAll);
        s += vals[i];
    }
#pragma unroll
    for (int off = 16; off > 0; off >>= 1)
        s += __shfl_xor_sync(0xffffffffu, s, off);
    if (lane == 0) red[wid] = s;
    __syncthreads();
    float sAll = 0.f;
#pragma unroll
    for (int w = 0; w < 8; w++) sAll += red[w];
    const float inv = 1.0f / sAll;

#pragma unroll
    for (int i = 0; i < 4; i++) {
        float4 v;
        v.x = vals[i * 4 + 0] * inv; v.y = vals[i * 4 + 1] * inv;
        v.z = vals[i * 4 + 2] * inv; v.w = vals[i * 4 + 3] * inv;
        reinterpret_cast<float4*>(p)[tid + i * 256] = v;
    }
}

// ---------------------------------------------------------------------------
extern "C" void kernel_launch(void* const* d_in, const int* in_sizes, int n_in,
                              void* d_out, int out_size)
{
    const float* q_in = (const float*)d_in[0];
    const float* k_in = (const float*)d_in[1];
    const float* v_in = (const float*)d_in[2];
    const float* Wq   = (const float*)d_in[3];
    const float* bq   = (const float*)d_in[4];
    const float* Wk   = (const float*)d_in[5];
    const float* bk   = (const float*)d_in[6];
    const float* Wv   = (const float*)d_in[7];
    const float* bv   = (const float*)d_in[8];
    float* out = (float*)d_out;

    float *gq, *gk, *gvt, *gs;
    cudaGetSymbolAddress((void**)&gq,  g_q);
    cudaGetSymbolAddress((void**)&gk,  g_k);
    cudaGetSymbolAddress((void**)&gvt, g_vt);
    cudaGetSymbolAddress((void**)&gs,  g_s);

    static bool attrDone = false;
    if (!attrDone) {
        cudaFuncSetAttribute(mma_gemm_nt<true,  false>,
                             cudaFuncAttributeMaxDynamicSharedMemorySize, SMEM_BYTES);
        cudaFuncSetAttribute(mma_gemm_nt<true,  true>,
                             cudaFuncAttributeMaxDynamicSharedMemorySize, SMEM_BYTES);
        cudaFuncSetAttribute(mma_gemm_nt<false, false>,
                             cudaFuncAttributeMaxDynamicSharedMemorySize, SMEM_BYTES);
        attrDone = true;
    }

    dim3 blk(512);

    // 1) projections: [16384,512] @ W^T + b   (V transposed into g_vt)
    {
        dim3 grd(EMB / 128, (BATCH * SEQ) / 128, 1);
        mma_gemm_nt<true, false><<<grd, blk, SMEM_BYTES>>>(
            q_in, Wq, bq, gq, EMB, EMB, EMB, EMB, 0, 0, 0);
        mma_gemm_nt<true, false><<<grd, blk, SMEM_BYTES>>>(
            k_in, Wk, bk, gk, EMB, EMB, EMB, EMB, 0, 0, 0);
        mma_gemm_nt<true, true><<<grd, blk, SMEM_BYTES>>>(
            v_in, Wv, bv, gvt, EMB, EMB, EMB, SEQ, 0, 0, 0);
    }

    // 2) scores[b] = q[b] @ k[b]^T
    {
        dim3 grd(SEQ / 128, SEQ / 128, BATCH);
        mma_gemm_nt<false, false><<<grd, blk, SMEM_BYTES>>>(
            gq, gk, nullptr, gs, EMB, EMB, EMB, SEQ,
            (long)SEQ * EMB, (long)SEQ * EMB, (long)SEQ * SEQ);
    }

    // 3) row softmax in place
    softmax_rows<<<BATCH * SEQ, 256>>>(gs);

    // 4) out[b] = attn[b] @ v[b]   (B = vT[b], NT form)
    {
        dim3 grd(EMB / 128, SEQ / 128, BATCH);
        mma_gemm_nt<false, false><<<grd, blk, SMEM_BYTES>>>(
            gs, gvt, nullptr, out, SEQ, SEQ, SEQ, EMB,
            (long)SEQ * SEQ, (long)EMB * SEQ, (long)SEQ * EMB);
    }
}

// round 6
// speedup vs baseline: 1.4068x; 1.2001x over previous
#include <cuda_runtime.h>
#include <math.h>

#define BATCH 4
#define SEQ   4096
#define EMB   512

// Scratch (__device__ globals: sanctioned, no runtime allocation)
__device__ float g_q [BATCH * SEQ * EMB];                 // 32 MB  [b*s][e]
__device__ float g_k [BATCH * SEQ * EMB];                 // 32 MB  [b*s][e]
__device__ float g_vt[BATCH * SEQ * EMB];                 // 32 MB  [b][e][s] (transposed)
__device__ float g_s [(size_t)BATCH * SEQ * SEQ];         // 256 MB scores/attn

__device__ __forceinline__ float cvt_tf32(float x) {
    asm("cvt.rna.tf32.f32 %0, %0;" : "+f"(x));
    return x;
}

#define TILE_F 4608                         // 128 * 36 floats per tile
#define SMEM_X2 (2 * 4 * TILE_F * 4)        // 147456 B (AsH,BsH,AsL,BsL x2 buf)
#define SMEM_X1 (2 * 2 * TILE_F * 4)        // 73728 B  (AsH,BsH x2 buf)

// ---------------------------------------------------------------------------
// TF32(x2 optional) tensor-core NT GEMM:  C[m,n]=sum_k A[m,k]*B[n,k] (+bias)
// Block tile 128x128, BK=32, 512 threads (16 warps 4m x 4n), warp tile 32x32.
// hi/lo split ONCE at staging into smem; double buffered, one sync per iter.
// X2: 3 mma (hh+hl+lh) per fragment pair; else single hh pass.
// TRANSC: scatter C transposed into [b][n][s] layout (V projection).
// ---------------------------------------------------------------------------
template <bool BIAS, bool TRANSC, bool X2>
__global__ void __launch_bounds__(512)
mma_gemm_nt(const float* __restrict__ A, const float* __restrict__ B,
            const float* __restrict__ bias, float* __restrict__ C,
            int K, int lda, int ldb, int ldc,
            long sA, long sB, long sC)
{
    extern __shared__ float smem[];
    const int STAGE_F = (X2 ? 4 : 2) * TILE_F;

    const int bz = blockIdx.z;
    A += (long)bz * sA;
    B += (long)bz * sB;
    C += (long)bz * sC;

    const int tid  = threadIdx.x;
    const int lane = tid & 31;
    const int wid  = tid >> 5;
    const int wm   = (wid & 3) * 32;
    const int wn   = (wid >> 2) * 32;
    const int m0   = blockIdx.y * 128;
    const int n0   = blockIdx.x * 128;

    // load mapping: 512 threads x 2 float4 per 128x32 tile
    const int r0c = tid >> 3;            // rows 0..63
    const int r1c = r0c + 64;            // rows 64..127
    const int k4  = (tid & 7) * 4;       // 0..28
    const float* Ag0 = A + (long)(m0 + r0c) * lda + k4;
    const float* Ag1 = A + (long)(m0 + r1c) * lda + k4;
    const float* Bg0 = B + (long)(n0 + r0c) * ldb + k4;
    const float* Bg1 = B + (long)(n0 + r1c) * ldb + k4;

    float acc[2][4][4];
#pragma unroll
    for (int i = 0; i < 2; i++)
#pragma unroll
        for (int j = 0; j < 4; j++)
#pragma unroll
            for (int r = 0; r < 4; r++) acc[i][j][r] = 0.f;

    // ldmatrix lane addressing (validated rounds 2-5)
    const unsigned smemU = (unsigned)__cvta_generic_to_shared(smem);
    const int r8 = lane & 7;
    const int hb = (lane >> 3) & 1;
    const int hf = lane >> 4;
    unsigned aOff[2], bOff[2];
#pragma unroll
    for (int mi = 0; mi < 2; mi++)
        aOff[mi] = ((wm + mi * 16 + r8 + hb * 8) * 36 + hf * 4) << 2;
#pragma unroll
    for (int p = 0; p < 2; p++)
        bOff[p] = ((wn + p * 16 + r8 + hf * 8) * 36 + hb * 4) << 2;

    const int niter = K >> 5;
    const int s0 = r0c * 36 + k4;
    const int s1 = r1c * 36 + k4;

    // stage one 128x32 A tile + B tile into buffer `buf` with hi/lo split
    auto splitStore = [&](int buf, float4 va0, float4 va1, float4 vb0, float4 vb1) {
        float* AsH = smem + buf * STAGE_F;
        float* BsH = AsH + TILE_F;
        float4 h;
        h = make_float4(cvt_tf32(va0.x), cvt_tf32(va0.y), cvt_tf32(va0.z), cvt_tf32(va0.w));
        *reinterpret_cast<float4*>(&AsH[s0]) = h;
        if (X2) {
            float* AsL = AsH + 2 * TILE_F;
            *reinterpret_cast<float4*>(&AsL[s0]) =
                make_float4(cvt_tf32(va0.x - h.x), cvt_tf32(va0.y - h.y),
                            cvt_tf32(va0.z - h.z), cvt_tf32(va0.w - h.w));
        }
        h = make_float4(cvt_tf32(va1.x), cvt_tf32(va1.y), cvt_tf32(va1.z), cvt_tf32(va1.w));
        *reinterpret_cast<float4*>(&AsH[s1]) = h;
        if (X2) {
            float* AsL = AsH + 2 * TILE_F;
            *reinterpret_cast<float4*>(&AsL[s1]) =
                make_float4(cvt_tf32(va1.x - h.x), cvt_tf32(va1.y - h.y),
                            cvt_tf32(va1.z - h.z), cvt_tf32(va1.w - h.w));
        }
        h = make_float4(cvt_tf32(vb0.x), cvt_tf32(vb0.y), cvt_tf32(vb0.z), cvt_tf32(vb0.w));
        *reinterpret_cast<float4*>(&BsH[s0]) = h;
        if (X2) {
            float* BsL = AsH + 3 * TILE_F;
            *reinterpret_cast<float4*>(&BsL[s0]) =
                make_float4(cvt_tf32(vb0.x - h.x), cvt_tf32(vb0.y - h.y),
                            cvt_tf32(vb0.z - h.z), cvt_tf32(vb0.w - h.w));
        }
        h = make_float4(cvt_tf32(vb1.x), cvt_tf32(vb1.y), cvt_tf32(vb1.z), cvt_tf32(vb1.w));
        *reinterpret_cast<float4*>(&BsH[s1]) = h;
        if (X2) {
            float* BsL = AsH + 3 * TILE_F;
            *reinterpret_cast<float4*>(&BsL[s1]) =
                make_float4(cvt_tf32(vb1.x - h.x), cvt_tf32(vb1.y - h.y),
                            cvt_tf32(vb1.z - h.z), cvt_tf32(vb1.w - h.w));
        }
    };

    // ---- prologue: tile 0 ----
    {
        float4 a0 = *reinterpret_cast<const float4*>(Ag0);
        float4 a1 = *reinterpret_cast<const float4*>(Ag1);
        float4 b0 = *reinterpret_cast<const float4*>(Bg0);
        float4 b1 = *reinterpret_cast<const float4*>(Bg1);
        splitStore(0, a0, a1, b0, b1);
    }
    __syncthreads();

    for (int it = 0; it < niter; it++) {
        const int cur = it & 1;

        float4 pa0, pa1, pb0, pb1;
        const bool more = (it + 1 < niter);
        if (more) {
            const int ko = (it + 1) * 32;
            pa0 = *reinterpret_cast<const float4*>(Ag0 + ko);
            pa1 = *reinterpret_cast<const float4*>(Ag1 + ko);
            pb0 = *reinterpret_cast<const float4*>(Bg0 + ko);
            pb1 = *reinterpret_cast<const float4*>(Bg1 + ko);
        }

        const unsigned stB = smemU + (unsigned)(cur * STAGE_F) * 4u;
        const unsigned aH = stB;
        const unsigned bH = stB + TILE_F * 4u;
        const unsigned aL = stB + 2u * TILE_F * 4u;
        const unsigned bL = stB + 3u * TILE_F * 4u;

#pragma unroll
        for (int ks = 0; ks < 4; ks++) {
            unsigned aFh[2][4], aFl[2][4];
            unsigned bFh[4][2], bFl[4][2];
#pragma unroll
            for (int mi = 0; mi < 2; mi++) {
                asm volatile(
                    "ldmatrix.sync.aligned.m8n8.x4.shared.b16 {%0,%1,%2,%3}, [%4];"
                    : "=r"(aFh[mi][0]), "=r"(aFh[mi][1]), "=r"(aFh[mi][2]), "=r"(aFh[mi][3])
                    : "r"(aH + aOff[mi] + ks * 32));
                if (X2) {
                    asm volatile(
                        "ldmatrix.sync.aligned.m8n8.x4.shared.b16 {%0,%1,%2,%3}, [%4];"
                        : "=r"(aFl[mi][0]), "=r"(aFl[mi][1]), "=r"(aFl[mi][2]), "=r"(aFl[mi][3])
                        : "r"(aL + aOff[mi] + ks * 32));
                }
            }
#pragma unroll
            for (int p = 0; p < 2; p++) {
                unsigned q0, q1, q2, q3;
                asm volatile(
                    "ldmatrix.sync.aligned.m8n8.x4.shared.b16 {%0,%1,%2,%3}, [%4];"
                    : "=r"(q0), "=r"(q1), "=r"(q2), "=r"(q3)
                    : "r"(bH + bOff[p] + ks * 32));
                bFh[2 * p][0] = q0; bFh[2 * p][1] = q1;
                bFh[2 * p + 1][0] = q2; bFh[2 * p + 1][1] = q3;
                if (X2) {
                    asm volatile(
                        "ldmatrix.sync.aligned.m8n8.x4.shared.b16 {%0,%1,%2,%3}, [%4];"
                        : "=r"(q0), "=r"(q1), "=r"(q2), "=r"(q3)
                        : "r"(bL + bOff[p] + ks * 32));
                    bFl[2 * p][0] = q0; bFl[2 * p][1] = q1;
                    bFl[2 * p + 1][0] = q2; bFl[2 * p + 1][1] = q3;
                }
            }

#define MMA(aa, bb, mi, nj)                                                   \
    asm volatile(                                                             \
        "mma.sync.aligned.m16n8k8.row.col.f32.tf32.tf32.f32 "                 \
        "{%0,%1,%2,%3}, {%4,%5,%6,%7}, {%8,%9}, {%0,%1,%2,%3};"               \
        : "+f"(acc[mi][nj][0]), "+f"(acc[mi][nj][1]),                         \
          "+f"(acc[mi][nj][2]), "+f"(acc[mi][nj][3])                          \
        : "r"(aa[mi][0]), "r"(aa[mi][1]), "r"(aa[mi][2]), "r"(aa[mi][3]),     \
          "r"(bb[nj][0]), "r"(bb[nj][1]))

#pragma unroll
            for (int mi = 0; mi < 2; mi++)
#pragma unroll
                for (int nj = 0; nj < 4; nj++) {
                    if (X2) {
                        MMA(aFh, bFl, mi, nj);   // hi*lo
                        MMA(aFl, bFh, mi, nj);   // lo*hi
                    }
                    MMA(aFh, bFh, mi, nj);       // hi*hi
                }
#undef MMA
        }

        if (more)
            splitStore(1 - cur, pa0, pa1, pb0, pb1);
        __syncthreads();
    }

    // epilogue
    const int g = lane >> 2;
    const int t = lane & 3;
#pragma unroll
    for (int nj = 0; nj < 4; nj++) {
        const int col = n0 + wn + nj * 8 + t * 2;
        float b0 = 0.f, b1 = 0.f;
        if (BIAS) { b0 = bias[col]; b1 = bias[col + 1]; }
#pragma unroll
        for (int mi = 0; mi < 2; mi++) {
            const int row = m0 + wm + mi * 16 + g;
            float c0 = acc[mi][nj][0] + b0;
            float c1 = acc[mi][nj][1] + b1;
            float c2 = acc[mi][nj][2] + b0;
            float c3 = acc[mi][nj][3] + b1;
            if (!TRANSC) {
                *reinterpret_cast<float2*>(&C[(long)row * ldc + col]) = make_float2(c0, c1);
                *reinterpret_cast<float2*>(&C[(long)(row + 8) * ldc + col]) = make_float2(c2, c3);
            } else {
                const int bb = row >> 12;
                const int s  = row & 4095;
                float* Cb = C + (long)bb * EMB * SEQ + s;
                Cb[(long)col * SEQ]           = c0;
                Cb[(long)(col + 1) * SEQ]     = c1;
                Cb[(long)col * SEQ + 8]       = c2;
                Cb[(long)(col + 1) * SEQ + 8] = c3;
            }
        }
    }
}

// ---------------------------------------------------------------------------
// Row softmax, in place. One block per 4096-col row, 256 threads.
// ---------------------------------------------------------------------------
__global__ void __launch_bounds__(256)
softmax_rows(float* __restrict__ S)
{
    const long row = blockIdx.x;
    float* p = S + row * (long)SEQ;
    const int tid  = threadIdx.x;
    const int lane = tid & 31;
    const int wid  = tid >> 5;

    float vals[16];
    float m = -3.0e38f;
#pragma unroll
    for (int i = 0; i < 4; i++) {
        float4 v = reinterpret_cast<float4*>(p)[tid + i * 256];
        vals[i * 4 + 0] = v.x; vals[i * 4 + 1] = v.y;
        vals[i * 4 + 2] = v.z; vals[i * 4 + 3] = v.w;
        m = fmaxf(m, fmaxf(fmaxf(v.x, v.y), fmaxf(v.z, v.w)));
    }

    __shared__ float red[8];
#pragma unroll
    for (int off = 16; off > 0; off >>= 1)
        m = fmaxf(m, __shfl_xor_sync(0xffffffffu, m, off));
    if (lane == 0) red[wid] = m;
    __syncthreads();
    float mAll = red[0];
#pragma unroll
    for (int w = 1; w < 8; w++) mAll = fmaxf(mAll, red[w]);
    __syncthreads();

    float s = 0.f;
#pragma unroll
    for (int i = 0; i < 16; i++) {
        vals[i] = __expf(vals[i] - mAll);
        s += vals[i];
    }
#pragma unroll
    for (int off = 16; off > 0; off >>= 1)
        s += __shfl_xor_sync(0xffffffffu, s, off);
    if (lane == 0) red[wid] = s;
    __syncthreads();
    float sAll = 0.f;
#pragma unroll
    for (int w = 0; w < 8; w++) sAll += red[w];
    const float inv = 1.0f / sAll;

#pragma unroll
    for (int i = 0; i < 4; i++) {
        float4 v;
        v.x = vals[i * 4 + 0] * inv; v.y = vals[i * 4 + 1] * inv;
        v.z = vals[i * 4 + 2] * inv; v.w = vals[i * 4 + 3] * inv;
        reinterpret_cast<float4*>(p)[tid + i * 256] = v;
    }
}

// ---------------------------------------------------------------------------
extern "C" void kernel_launch(void* const* d_in, const int* in_sizes, int n_in,
                              void* d_out, int out_size)
{
    const float* q_in = (const float*)d_in[0];
    const float* k_in = (const float*)d_in[1];
    const float* v_in = (const float*)d_in[2];
    const float* Wq   = (const float*)d_in[3];
    const float* bq   = (const float*)d_in[4];
    const float* Wk   = (const float*)d_in[5];
    const float* bk   = (const float*)d_in[6];
    const float* Wv   = (const float*)d_in[7];
    const float* bv   = (const float*)d_in[8];
    float* out = (float*)d_out;

    float *gq, *gk, *gvt, *gs;
    cudaGetSymbolAddress((void**)&gq,  g_q);
    cudaGetSymbolAddress((void**)&gk,  g_k);
    cudaGetSymbolAddress((void**)&gvt, g_vt);
    cudaGetSymbolAddress((void**)&gs,  g_s);

    static bool attrDone = false;
    if (!attrDone) {
        cudaFuncSetAttribute(mma_gemm_nt<true,  false, true>,
                             cudaFuncAttributeMaxDynamicSharedMemorySize, SMEM_X2);
        cudaFuncSetAttribute(mma_gemm_nt<true,  true,  true>,
                             cudaFuncAttributeMaxDynamicSharedMemorySize, SMEM_X2);
        cudaFuncSetAttribute(mma_gemm_nt<false, false, true>,
                             cudaFuncAttributeMaxDynamicSharedMemorySize, SMEM_X2);
        cudaFuncSetAttribute(mma_gemm_nt<false, false, false>,
                             cudaFuncAttributeMaxDynamicSharedMemorySize, SMEM_X1);
        attrDone = true;
    }

    dim3 blk(512);

    // 1) projections (all x2): [16384,512] @ W^T + b  (V transposed into g_vt)
    {
        dim3 grd(EMB / 128, (BATCH * SEQ) / 128, 1);
        mma_gemm_nt<true, false, true><<<grd, blk, SMEM_X2>>>(
            q_in, Wq, bq, gq, EMB, EMB, EMB, EMB, 0, 0, 0);
        mma_gemm_nt<true, false, true><<<grd, blk, SMEM_X2>>>(
            k_in, Wk, bk, gk, EMB, EMB, EMB, EMB, 0, 0, 0);
        mma_gemm_nt<true, true, true><<<grd, blk, SMEM_X2>>>(
            v_in, Wv, bv, gvt, EMB, EMB, EMB, SEQ, 0, 0, 0);
    }

    // 2) scores[b] = q[b] @ k[b]^T  (x2: score path is error-amplified)
    {
        dim3 grd(SEQ / 128, SEQ / 128, BATCH);
        mma_gemm_nt<false, false, true><<<grd, blk, SMEM_X2>>>(
            gq, gk, nullptr, gs, EMB, EMB, EMB, SEQ,
            (long)SEQ * EMB, (long)SEQ * EMB, (long)SEQ * SEQ);
    }

    // 3) row softmax in place
    softmax_rows<<<BATCH * SEQ, 256>>>(gs);

    // 4) out[b] = attn[b] @ v[b]  (x1: post-softmax, no amplification)
    {
        dim3 grd(EMB / 128, SEQ / 128, BATCH);
        mma_gemm_nt<false, false, false><<<grd, blk, SMEM_X1>>>(
            gs, gvt, nullptr, out, SEQ, SEQ, SEQ, EMB,
            (long)SEQ * SEQ, (long)EMB * SEQ, (long)SEQ * EMB);
    }
}

// round 7
// speedup vs baseline: 1.6921x; 1.2028x over previous
#include <cuda_runtime.h>
#include <cuda_bf16.h>
#include <math.h>

#define BATCH 4
#define SEQ   4096
#define EMB   512

// Scratch (__device__ globals: sanctioned, no runtime allocation)
__device__ float g_q [BATCH * SEQ * EMB];                 // 32 MB  [b*s][e]
__device__ float g_k [BATCH * SEQ * EMB];                 // 32 MB  [b*s][e]
__device__ float g_vt[BATCH * SEQ * EMB];                 // 32 MB  [b][e][s] (transposed)
__device__ float g_s [(size_t)BATCH * SEQ * SEQ];         // 256 MB scores/attn

// bf16 tiles: 128 rows x 40 bf16 (BK=32 + pad 8) -> row stride 80B,
// conflict-free for ldmatrix (bank starts 0,20,8,28,16,4,24,12).
#define TILE_U  2560                        // u32 per tile (128 * 20)
#define STAGE_U (4 * TILE_U)                // Ah, Bh, Al, Bl
#define SMEM_BYTES (2 * STAGE_U * 4)        // 81920 B (double buffer)

// split x into bf16 hi + bf16 lo (l = bf16(x - float(h))), pack 2 at a time
__device__ __forceinline__ void split2(float x, float y, unsigned& h, unsigned& l) {
    __nv_bfloat16 hx = __float2bfloat16_rn(x);
    __nv_bfloat16 hy = __float2bfloat16_rn(y);
    __nv_bfloat16 lx = __float2bfloat16_rn(x - __bfloat162float(hx));
    __nv_bfloat16 ly = __float2bfloat16_rn(y - __bfloat162float(hy));
    h = ((unsigned)__bfloat16_as_ushort(hy) << 16) | __bfloat16_as_ushort(hx);
    l = ((unsigned)__bfloat16_as_ushort(ly) << 16) | __bfloat16_as_ushort(lx);
}

// ---------------------------------------------------------------------------
// BF16(x2) tensor-core NT GEMM:  C[m,n] = sum_k A[m,k]*B[n,k] (+bias[n])
// Block tile 128x128, BK=32, 512 threads (16 warps 4m x 4n), warp tile 32x32.
// fp32 -> bf16 hi/lo split ONCE at staging into smem; double buffered, one
// sync per iter. mma.m16n8k16.bf16, 3 passes (hh+hl+lh) per fragment pair.
// TRANSC: scatter C transposed into [b][n][s] layout (V projection).
// ---------------------------------------------------------------------------
template <bool BIAS, bool TRANSC>
__global__ void __launch_bounds__(512)
mma_gemm_nt(const float* __restrict__ A, const float* __restrict__ B,
            const float* __restrict__ bias, float* __restrict__ C,
            int K, int lda, int ldb, int ldc,
            long sA, long sB, long sC)
{
    extern __shared__ unsigned su[];

    const int bz = blockIdx.z;
    A += (long)bz * sA;
    B += (long)bz * sB;
    C += (long)bz * sC;

    const int tid  = threadIdx.x;
    const int lane = tid & 31;
    const int wid  = tid >> 5;
    const int wm   = (wid & 3) * 32;
    const int wn   = (wid >> 2) * 32;
    const int m0   = blockIdx.y * 128;
    const int n0   = blockIdx.x * 128;

    // global load mapping: 512 threads x 2 float4 per 128x32 tile
    const int r0c = tid >> 3;            // rows 0..63
    const int r1c = r0c + 64;            // rows 64..127
    const int k4  = (tid & 7) * 4;       // 0..28 (fp32/bf16 elements)
    const float* Ag0 = A + (long)(m0 + r0c) * lda + k4;
    const float* Ag1 = A + (long)(m0 + r1c) * lda + k4;
    const float* Bg0 = B + (long)(n0 + r0c) * ldb + k4;
    const float* Bg1 = B + (long)(n0 + r1c) * ldb + k4;

    float acc[2][4][4];
#pragma unroll
    for (int i = 0; i < 2; i++)
#pragma unroll
        for (int j = 0; j < 4; j++)
#pragma unroll
            for (int r = 0; r < 4; r++) acc[i][j][r] = 0.f;

    // ldmatrix lane addressing (bf16 variant of validated tf32 mapping)
    const unsigned smemU = (unsigned)__cvta_generic_to_shared(su);
    const int r8 = lane & 7;
    const int hb = (lane >> 3) & 1;
    const int hf = lane >> 4;
    // A x4: a0=rows0-7 k0-7, a1=rows8-15 k0-7, a2=rows0-7 k8-15, a3=rows8-15 k8-15
    unsigned aOff[2], bOff[2];
#pragma unroll
    for (int mi = 0; mi < 2; mi++)
        aOff[mi] = ((wm + mi * 16 + r8 + hb * 8) * 40 + hf * 8) * 2;   // bytes
    // B x4: q0=n0-7 klo, q1=n0-7 khi, q2=n8-15 klo, q3=n8-15 khi
#pragma unroll
    for (int p = 0; p < 2; p++)
        bOff[p] = ((wn + p * 16 + r8 + hf * 8) * 40) * 2 + hb * 16;    // bytes

    const int niter = K >> 5;
    const int s0 = r0c * 20 + (tid & 7) * 2;   // u32 index in tile
    const int s1 = r1c * 20 + (tid & 7) * 2;

    auto splitStore = [&](int buf, float4 va0, float4 va1, float4 vb0, float4 vb1) {
        unsigned* AsH = su + buf * STAGE_U;
        unsigned* BsH = AsH + TILE_U;
        unsigned* AsL = AsH + 2 * TILE_U;
        unsigned* BsL = AsH + 3 * TILE_U;
        unsigned h0, h1, l0, l1;
        split2(va0.x, va0.y, h0, l0); split2(va0.z, va0.w, h1, l1);
        *reinterpret_cast<uint2*>(&AsH[s0]) = make_uint2(h0, h1);
        *reinterpret_cast<uint2*>(&AsL[s0]) = make_uint2(l0, l1);
        split2(va1.x, va1.y, h0, l0); split2(va1.z, va1.w, h1, l1);
        *reinterpret_cast<uint2*>(&AsH[s1]) = make_uint2(h0, h1);
        *reinterpret_cast<uint2*>(&AsL[s1]) = make_uint2(l0, l1);
        split2(vb0.x, vb0.y, h0, l0); split2(vb0.z, vb0.w, h1, l1);
        *reinterpret_cast<uint2*>(&BsH[s0]) = make_uint2(h0, h1);
        *reinterpret_cast<uint2*>(&BsL[s0]) = make_uint2(l0, l1);
        split2(vb1.x, vb1.y, h0, l0); split2(vb1.z, vb1.w, h1, l1);
        *reinterpret_cast<uint2*>(&BsH[s1]) = make_uint2(h0, h1);
        *reinterpret_cast<uint2*>(&BsL[s1]) = make_uint2(l0, l1);
    };

    // ---- prologue: tile 0 ----
    {
        float4 a0 = *reinterpret_cast<const float4*>(Ag0);
        float4 a1 = *reinterpret_cast<const float4*>(Ag1);
        float4 b0 = *reinterpret_cast<const float4*>(Bg0);
        float4 b1 = *reinterpret_cast<const float4*>(Bg1);
        splitStore(0, a0, a1, b0, b1);
    }
    __syncthreads();

    for (int it = 0; it < niter; it++) {
        const int cur = it & 1;

        float4 pa0, pa1, pb0, pb1;
        const bool more = (it + 1 < niter);
        if (more) {
            const int ko = (it + 1) * 32;
            pa0 = *reinterpret_cast<const float4*>(Ag0 + ko);
            pa1 = *reinterpret_cast<const float4*>(Ag1 + ko);
            pb0 = *reinterpret_cast<const float4*>(Bg0 + ko);
            pb1 = *reinterpret_cast<const float4*>(Bg1 + ko);
        }

        const unsigned stB = smemU + (unsigned)(cur * STAGE_U) * 4u;
        const unsigned aH = stB;
        const unsigned bH = stB + TILE_U * 4u;
        const unsigned aL = stB + 2u * TILE_U * 4u;
        const unsigned bL = stB + 3u * TILE_U * 4u;

#pragma unroll
        for (int ks = 0; ks < 2; ks++) {          // two k16 steps per BK=32
            unsigned aFh[2][4], aFl[2][4];
            unsigned bFh[4][2], bFl[4][2];
#pragma unroll
            for (int mi = 0; mi < 2; mi++) {
                asm volatile(
                    "ldmatrix.sync.aligned.m8n8.x4.shared.b16 {%0,%1,%2,%3}, [%4];"
                    : "=r"(aFh[mi][0]), "=r"(aFh[mi][1]), "=r"(aFh[mi][2]), "=r"(aFh[mi][3])
                    : "r"(aH + aOff[mi] + ks * 32));
                asm volatile(
                    "ldmatrix.sync.aligned.m8n8.x4.shared.b16 {%0,%1,%2,%3}, [%4];"
                    : "=r"(aFl[mi][0]), "=r"(aFl[mi][1]), "=r"(aFl[mi][2]), "=r"(aFl[mi][3])
                    : "r"(aL + aOff[mi] + ks * 32));
            }
#pragma unroll
            for (int p = 0; p < 2; p++) {
                unsigned q0, q1, q2, q3;
                asm volatile(
                    "ldmatrix.sync.aligned.m8n8.x4.shared.b16 {%0,%1,%2,%3}, [%4];"
                    : "=r"(q0), "=r"(q1), "=r"(q2), "=r"(q3)
                    : "r"(bH + bOff[p] + ks * 32));
                bFh[2 * p][0] = q0; bFh[2 * p][1] = q1;
                bFh[2 * p + 1][0] = q2; bFh[2 * p + 1][1] = q3;
                asm volatile(
                    "ldmatrix.sync.aligned.m8n8.x4.shared.b16 {%0,%1,%2,%3}, [%4];"
                    : "=r"(q0), "=r"(q1), "=r"(q2), "=r"(q3)
                    : "r"(bL + bOff[p] + ks * 32));
                bFl[2 * p][0] = q0; bFl[2 * p][1] = q1;
                bFl[2 * p + 1][0] = q2; bFl[2 * p + 1][1] = q3;
            }

#define MMA(aa, bb, mi, nj)                                                   \
    asm volatile(                                                             \
        "mma.sync.aligned.m16n8k16.row.col.f32.bf16.bf16.f32 "                \
        "{%0,%1,%2,%3}, {%4,%5,%6,%7}, {%8,%9}, {%0,%1,%2,%3};"               \
        : "+f"(acc[mi][nj][0]), "+f"(acc[mi][nj][1]),                         \
          "+f"(acc[mi][nj][2]), "+f"(acc[mi][nj][3])                          \
        : "r"(aa[mi][0]), "r"(aa[mi][1]), "r"(aa[mi][2]), "r"(aa[mi][3]),     \
          "r"(bb[nj][0]), "r"(bb[nj][1]))

#pragma unroll
            for (int mi = 0; mi < 2; mi++)
#pragma unroll
                for (int nj = 0; nj < 4; nj++) {
                    MMA(aFh, bFl, mi, nj);   // hi*lo
                    MMA(aFl, bFh, mi, nj);   // lo*hi
                    MMA(aFh, bFh, mi, nj);   // hi*hi
                }
#undef MMA
        }

        if (more)
            splitStore(1 - cur, pa0, pa1, pb0, pb1);
        __syncthreads();
    }

    // epilogue
    const int g = lane >> 2;
    const int t = lane & 3;
#pragma unroll
    for (int nj = 0; nj < 4; nj++) {
        const int col = n0 + wn + nj * 8 + t * 2;
        float b0 = 0.f, b1 = 0.f;
        if (BIAS) { b0 = bias[col]; b1 = bias[col + 1]; }
#pragma unroll
        for (int mi = 0; mi < 2; mi++) {
            const int row = m0 + wm + mi * 16 + g;
            float c0 = acc[mi][nj][0] + b0;
            float c1 = acc[mi][nj][1] + b1;
            float c2 = acc[mi][nj][2] + b0;
            float c3 = acc[mi][nj][3] + b1;
            if (!TRANSC) {
                *reinterpret_cast<float2*>(&C[(long)row * ldc + col]) = make_float2(c0, c1);
                *reinterpret_cast<float2*>(&C[(long)(row + 8) * ldc + col]) = make_float2(c2, c3);
            } else {
                const int bb = row >> 12;
                const int s  = row & 4095;
                float* Cb = C + (long)bb * EMB * SEQ + s;
                Cb[(long)col * SEQ]           = c0;
                Cb[(long)(col + 1) * SEQ]     = c1;
                Cb[(long)col * SEQ + 8]       = c2;
                Cb[(long)(col + 1) * SEQ + 8] = c3;
            }
        }
    }
}

// ---------------------------------------------------------------------------
// Row softmax, in place. One block per 4096-col row, 256 threads.
// ---------------------------------------------------------------------------
__global__ void __launch_bounds__(256)
softmax_rows(float* __restrict__ S)
{
    const long row = blockIdx.x;
    float* p = S + row * (long)SEQ;
    const int tid  = threadIdx.x;
    const int lane = tid & 31;
    const int wid  = tid >> 5;

    float vals[16];
    float m = -3.0e38f;
#pragma unroll
    for (int i = 0; i < 4; i++) {
        float4 v = reinterpret_cast<float4*>(p)[tid + i * 256];
        vals[i * 4 + 0] = v.x; vals[i * 4 + 1] = v.y;
        vals[i * 4 + 2] = v.z; vals[i * 4 + 3] = v.w;
        m = fmaxf(m, fmaxf(fmaxf(v.x, v.y), fmaxf(v.z, v.w)));
    }

    __shared__ float red[8];
#pragma unroll
    for (int off = 16; off > 0; off >>= 1)
        m = fmaxf(m, __shfl_xor_sync(0xffffffffu, m, off));
    if (lane == 0) red[wid] = m;
    __syncthreads();
    float mAll = red[0];
#pragma unroll
    for (int w = 1; w < 8; w++) mAll = fmaxf(mAll, red[w]);
    __syncthreads();

    float s = 0.f;
#pragma unroll
    for (int i = 0; i < 16; i++) {
        vals[i] = __expf(vals[i] - mAll);
        s += vals[i];
    }
#pragma unroll
    for (int off = 16; off > 0; off >>= 1)
        s += __shfl_xor_sync(0xffffffffu, s, off);
    if (lane == 0) red[wid] = s;
    __syncthreads();
    float sAll = 0.f;
#pragma unroll
    for (int w = 0; w < 8; w++) sAll += red[w];
    const float inv = 1.0f / sAll;

#pragma unroll
    for (int i = 0; i < 4; i++) {
        float4 v;
        v.x = vals[i * 4 + 0] * inv; v.y = vals[i * 4 + 1] * inv;
        v.z = vals[i * 4 + 2] * inv; v.w = vals[i * 4 + 3] * inv;
        reinterpret_cast<float4*>(p)[tid + i * 256] = v;
    }
}

// ---------------------------------------------------------------------------
extern "C" void kernel_launch(void* const* d_in, const int* in_sizes, int n_in,
                              void* d_out, int out_size)
{
    const float* q_in = (const float*)d_in[0];
    const float* k_in = (const float*)d_in[1];
    const float* v_in = (const float*)d_in[2];
    const float* Wq   = (const float*)d_in[3];
    const float* bq   = (const float*)d_in[4];
    const float* Wk   = (const float*)d_in[5];
    const float* bk   = (const float*)d_in[6];
    const float* Wv   = (const float*)d_in[7];
    const float* bv   = (const float*)d_in[8];
    float* out = (float*)d_out;

    float *gq, *gk, *gvt, *gs;
    cudaGetSymbolAddress((void**)&gq,  g_q);
    cudaGetSymbolAddress((void**)&gk,  g_k);
    cudaGetSymbolAddress((void**)&gvt, g_vt);
    cudaGetSymbolAddress((void**)&gs,  g_s);

    static bool attrDone = false;
    if (!attrDone) {
        cudaFuncSetAttribute(mma_gemm_nt<true,  false>,
                             cudaFuncAttributeMaxDynamicSharedMemorySize, SMEM_BYTES);
        cudaFuncSetAttribute(mma_gemm_nt<true,  true>,
                             cudaFuncAttributeMaxDynamicSharedMemorySize, SMEM_BYTES);
        cudaFuncSetAttribute(mma_gemm_nt<false, false>,
                             cudaFuncAttributeMaxDynamicSharedMemorySize, SMEM_BYTES);
        attrDone = true;
    }

    dim3 blk(512);

    // 1) projections: [16384,512] @ W^T + b  (V transposed into g_vt)
    {
        dim3 grd(EMB / 128, (BATCH * SEQ) / 128, 1);
        mma_gemm_nt<true, false><<<grd, blk, SMEM_BYTES>>>(
            q_in, Wq, bq, gq, EMB, EMB, EMB, EMB, 0, 0, 0);
        mma_gemm_nt<true, false><<<grd, blk, SMEM_BYTES>>>(
            k_in, Wk, bk, gk, EMB, EMB, EMB, EMB, 0, 0, 0);
        mma_gemm_nt<true, true><<<grd, blk, SMEM_BYTES>>>(
            v_in, Wv, bv, gvt, EMB, EMB, EMB, SEQ, 0, 0, 0);
    }

    // 2) scores[b] = q[b] @ k[b]^T
    {
        dim3 grd(SEQ / 128, SEQ / 128, BATCH);
        mma_gemm_nt<false, false><<<grd, blk, SMEM_BYTES>>>(
            gq, gk, nullptr, gs, EMB, EMB, EMB, SEQ,
            (long)SEQ * EMB, (long)SEQ * EMB, (long)SEQ * SEQ);
    }

    // 3) row softmax in place
    softmax_rows<<<BATCH * SEQ, 256>>>(gs);

    // 4) out[b] = attn[b] @ v[b]  (B = vT[b], NT form)
    {
        dim3 grd(EMB / 128, SEQ / 128, BATCH);
        mma_gemm_nt<false, false><<<grd, blk, SMEM_BYTES>>>(
            gs, gvt, nullptr, out, SEQ, SEQ, SEQ, EMB,
            (long)SEQ * SEQ, (long)EMB * SEQ, (long)SEQ * EMB);
    }
}

// round 8
// speedup vs baseline: 1.8679x; 1.1038x over previous
#include <cuda_runtime.h>
#include <cuda_bf16.h>
#include <math.h>

#define BATCH 4
#define SEQ   4096
#define EMB   512

// Scratch (__device__ globals: sanctioned, no runtime allocation)
__device__ float g_s[(size_t)BATCH * SEQ * SEQ];                  // 256 MB scores
__device__ __nv_bfloat16 g_qh[BATCH * SEQ * EMB], g_ql[BATCH * SEQ * EMB];
__device__ __nv_bfloat16 g_kh[BATCH * SEQ * EMB], g_kl[BATCH * SEQ * EMB];
__device__ __nv_bfloat16 g_vth[BATCH * SEQ * EMB], g_vtl[BATCH * SEQ * EMB];  // [b][e][s]
__device__ __nv_bfloat16 g_ph[(size_t)BATCH * SEQ * SEQ];         // 128 MB attn hi
__device__ __nv_bfloat16 g_pl[(size_t)BATCH * SEQ * SEQ];         // 128 MB attn lo

__device__ __forceinline__ unsigned packbf(__nv_bfloat16 a, __nv_bfloat16 b) {
    return ((unsigned)__bfloat16_as_ushort(b) << 16) | __bfloat16_as_ushort(a);
}
__device__ __forceinline__ void split2(float x, float y, unsigned& h, unsigned& l) {
    __nv_bfloat16 hx = __float2bfloat16_rn(x);
    __nv_bfloat16 hy = __float2bfloat16_rn(y);
    __nv_bfloat16 lx = __float2bfloat16_rn(x - __bfloat162float(hx));
    __nv_bfloat16 ly = __float2bfloat16_rn(y - __bfloat162float(hy));
    h = packbf(hx, hy);
    l = packbf(lx, ly);
}
__device__ __forceinline__ void cp16(unsigned dst, const void* src) {
    asm volatile("cp.async.cg.shared.global [%0], [%1], 16;" :: "r"(dst), "l"(src));
}

#define MMABF(aa, bb, mi, nj)                                                 \
    asm volatile(                                                             \
        "mma.sync.aligned.m16n8k16.row.col.f32.bf16.bf16.f32 "                \
        "{%0,%1,%2,%3}, {%4,%5,%6,%7}, {%8,%9}, {%0,%1,%2,%3};"               \
        : "+f"(acc[mi][nj][0]), "+f"(acc[mi][nj][1]),                         \
          "+f"(acc[mi][nj][2]), "+f"(acc[mi][nj][3])                          \
        : "r"(aa[mi][0]), "r"(aa[mi][1]), "r"(aa[mi][2]), "r"(aa[mi][3]),     \
          "r"(bb[nj][0]), "r"(bb[nj][1]))

// ===========================================================================
// Projection GEMM (fp32 in, split-bf16 out): C = A @ B^T + bias
// Round-7 validated structure: 128x128 tile, BK=32, 512 thr, split at staging.
// Epilogue writes hi/lo bf16 arrays; TRANSC scatters into [b][e][s].
// ===========================================================================
#define PTILE_U  2560                        // u32 per tile (128 rows * 20)
#define PSTAGE_U (4 * PTILE_U)
#define PSMEM    (2 * PSTAGE_U * 4)          // 81920 B

template <bool TRANSC>
__global__ void __launch_bounds__(512)
proj_gemm(const float* __restrict__ A, const float* __restrict__ B,
          const float* __restrict__ bias,
          __nv_bfloat16* __restrict__ Ch, __nv_bfloat16* __restrict__ Cl,
          int K, int lda, int ldb, int ldc)
{
    extern __shared__ unsigned su[];

    const int tid  = threadIdx.x;
    const int lane = tid & 31;
    const int wid  = tid >> 5;
    const int wm   = (wid & 3) * 32;
    const int wn   = (wid >> 2) * 32;
    const int m0   = blockIdx.y * 128;
    const int n0   = blockIdx.x * 128;

    const int r0c = tid >> 3;
    const int r1c = r0c + 64;
    const int k4  = (tid & 7) * 4;
    const float* Ag0 = A + (long)(m0 + r0c) * lda + k4;
    const float* Ag1 = A + (long)(m0 + r1c) * lda + k4;
    const float* Bg0 = B + (long)(n0 + r0c) * ldb + k4;
    const float* Bg1 = B + (long)(n0 + r1c) * ldb + k4;

    float acc[2][4][4];
#pragma unroll
    for (int i = 0; i < 2; i++)
#pragma unroll
        for (int j = 0; j < 4; j++)
#pragma unroll
            for (int r = 0; r < 4; r++) acc[i][j][r] = 0.f;

    const unsigned smemU = (unsigned)__cvta_generic_to_shared(su);
    const int r8 = lane & 7;
    const int hb = (lane >> 3) & 1;
    const int hf = lane >> 4;
    unsigned aOff[2], bOff[2];
#pragma unroll
    for (int mi = 0; mi < 2; mi++)
        aOff[mi] = ((wm + mi * 16 + r8 + hb * 8) * 40 + hf * 8) * 2;
#pragma unroll
    for (int p = 0; p < 2; p++)
        bOff[p] = ((wn + p * 16 + r8 + hf * 8) * 40) * 2 + hb * 16;

    const int niter = K >> 5;
    const int s0 = r0c * 20 + (tid & 7) * 2;
    const int s1 = r1c * 20 + (tid & 7) * 2;

    auto splitStore = [&](int buf, float4 va0, float4 va1, float4 vb0, float4 vb1) {
        unsigned* AsH = su + buf * PSTAGE_U;
        unsigned* BsH = AsH + PTILE_U;
        unsigned* AsL = AsH + 2 * PTILE_U;
        unsigned* BsL = AsH + 3 * PTILE_U;
        unsigned h0, h1, l0, l1;
        split2(va0.x, va0.y, h0, l0); split2(va0.z, va0.w, h1, l1);
        *reinterpret_cast<uint2*>(&AsH[s0]) = make_uint2(h0, h1);
        *reinterpret_cast<uint2*>(&AsL[s0]) = make_uint2(l0, l1);
        split2(va1.x, va1.y, h0, l0); split2(va1.z, va1.w, h1, l1);
        *reinterpret_cast<uint2*>(&AsH[s1]) = make_uint2(h0, h1);
        *reinterpret_cast<uint2*>(&AsL[s1]) = make_uint2(l0, l1);
        split2(vb0.x, vb0.y, h0, l0); split2(vb0.z, vb0.w, h1, l1);
        *reinterpret_cast<uint2*>(&BsH[s0]) = make_uint2(h0, h1);
        *reinterpret_cast<uint2*>(&BsL[s0]) = make_uint2(l0, l1);
        split2(vb1.x, vb1.y, h0, l0); split2(vb1.z, vb1.w, h1, l1);
        *reinterpret_cast<uint2*>(&BsH[s1]) = make_uint2(h0, h1);
        *reinterpret_cast<uint2*>(&BsL[s1]) = make_uint2(l0, l1);
    };

    {
        float4 a0 = *reinterpret_cast<const float4*>(Ag0);
        float4 a1 = *reinterpret_cast<const float4*>(Ag1);
        float4 b0 = *reinterpret_cast<const float4*>(Bg0);
        float4 b1 = *reinterpret_cast<const float4*>(Bg1);
        splitStore(0, a0, a1, b0, b1);
    }
    __syncthreads();

    for (int it = 0; it < niter; it++) {
        const int cur = it & 1;
        float4 pa0, pa1, pb0, pb1;
        const bool more = (it + 1 < niter);
        if (more) {
            const int ko = (it + 1) * 32;
            pa0 = *reinterpret_cast<const float4*>(Ag0 + ko);
            pa1 = *reinterpret_cast<const float4*>(Ag1 + ko);
            pb0 = *reinterpret_cast<const float4*>(Bg0 + ko);
            pb1 = *reinterpret_cast<const float4*>(Bg1 + ko);
        }

        const unsigned stB = smemU + (unsigned)(cur * PSTAGE_U) * 4u;
        const unsigned aH = stB;
        const unsigned bH = stB + PTILE_U * 4u;
        const unsigned aL = stB + 2u * PTILE_U * 4u;
        const unsigned bL = stB + 3u * PTILE_U * 4u;

#pragma unroll
        for (int ks = 0; ks < 2; ks++) {
            unsigned aFh[2][4], aFl[2][4];
            unsigned bFh[4][2], bFl[4][2];
#pragma unroll
            for (int mi = 0; mi < 2; mi++) {
                asm volatile("ldmatrix.sync.aligned.m8n8.x4.shared.b16 {%0,%1,%2,%3}, [%4];"
                    : "=r"(aFh[mi][0]), "=r"(aFh[mi][1]), "=r"(aFh[mi][2]), "=r"(aFh[mi][3])
                    : "r"(aH + aOff[mi] + ks * 32));
                asm volatile("ldmatrix.sync.aligned.m8n8.x4.shared.b16 {%0,%1,%2,%3}, [%4];"
                    : "=r"(aFl[mi][0]), "=r"(aFl[mi][1]), "=r"(aFl[mi][2]), "=r"(aFl[mi][3])
                    : "r"(aL + aOff[mi] + ks * 32));
            }
#pragma unroll
            for (int p = 0; p < 2; p++) {
                unsigned q0, q1, q2, q3;
                asm volatile("ldmatrix.sync.aligned.m8n8.x4.shared.b16 {%0,%1,%2,%3}, [%4];"
                    : "=r"(q0), "=r"(q1), "=r"(q2), "=r"(q3)
                    : "r"(bH + bOff[p] + ks * 32));
                bFh[2 * p][0] = q0; bFh[2 * p][1] = q1;
                bFh[2 * p + 1][0] = q2; bFh[2 * p + 1][1] = q3;
                asm volatile("ldmatrix.sync.aligned.m8n8.x4.shared.b16 {%0,%1,%2,%3}, [%4];"
                    : "=r"(q0), "=r"(q1), "=r"(q2), "=r"(q3)
                    : "r"(bL + bOff[p] + ks * 32));
                bFl[2 * p][0] = q0; bFl[2 * p][1] = q1;
                bFl[2 * p + 1][0] = q2; bFl[2 * p + 1][1] = q3;
            }
#pragma unroll
            for (int mi = 0; mi < 2; mi++)
#pragma unroll
                for (int nj = 0; nj < 4; nj++) {
                    MMABF(aFh, bFl, mi, nj);
                    MMABF(aFl, bFh, mi, nj);
                    MMABF(aFh, bFh, mi, nj);
                }
        }

        if (more) splitStore(1 - cur, pa0, pa1, pb0, pb1);
        __syncthreads();
    }

    // epilogue: split-write
    const int g = lane >> 2;
    const int t = lane & 3;
#pragma unroll
    for (int nj = 0; nj < 4; nj++) {
        const int col = n0 + wn + nj * 8 + t * 2;
        const float b0 = bias[col];
        const float b1 = bias[col + 1];
#pragma unroll
        for (int mi = 0; mi < 2; mi++) {
            const int row = m0 + wm + mi * 16 + g;
            float c[4] = {acc[mi][nj][0] + b0, acc[mi][nj][1] + b1,
                          acc[mi][nj][2] + b0, acc[mi][nj][3] + b1};
            __nv_bfloat16 h[4], l[4];
#pragma unroll
            for (int q = 0; q < 4; q++) {
                h[q] = __float2bfloat16_rn(c[q]);
                l[q] = __float2bfloat16_rn(c[q] - __bfloat162float(h[q]));
            }
            if (!TRANSC) {
                *reinterpret_cast<unsigned*>(&Ch[(long)row * ldc + col])       = packbf(h[0], h[1]);
                *reinterpret_cast<unsigned*>(&Cl[(long)row * ldc + col])       = packbf(l[0], l[1]);
                *reinterpret_cast<unsigned*>(&Ch[(long)(row + 8) * ldc + col]) = packbf(h[2], h[3]);
                *reinterpret_cast<unsigned*>(&Cl[(long)(row + 8) * ldc + col]) = packbf(l[2], l[3]);
            } else {
                const int bb = row >> 12;
                const int s  = row & 4095;
                __nv_bfloat16* Cbh = Ch + (long)bb * EMB * SEQ + s;
                __nv_bfloat16* Cbl = Cl + (long)bb * EMB * SEQ + s;
                Cbh[(long)col * SEQ]           = h[0];
                Cbh[(long)(col + 1) * SEQ]     = h[1];
                Cbh[(long)col * SEQ + 8]       = h[2];
                Cbh[(long)(col + 1) * SEQ + 8] = h[3];
                Cbl[(long)col * SEQ]           = l[0];
                Cbl[(long)(col + 1) * SEQ]     = l[1];
                Cbl[(long)col * SEQ + 8]       = l[2];
                Cbl[(long)(col + 1) * SEQ + 8] = l[3];
            }
        }
    }
}

// ===========================================================================
// Pre-split bf16 GEMM: C[m,n] = sum_k (Ah+Al)[m,k]*(Bh+Bl)[n,k], fp32 out
// 128x128 tile, BK=64, 512 threads, cp.async double-buffer, no conversion.
// smem tiles: 128 rows x 72 bf16 (pad 8) -> conflict-free ldmatrix.
// ===========================================================================
#define GTILE_B 18432                        // bytes per tile (128 * 72 * 2)
#define GSTAGE_B (4 * GTILE_B)               // Ah, Bh, Al, Bl
#define GSMEM    (2 * GSTAGE_B)              // 147456 B

__global__ void __launch_bounds__(512)
gemm_bf16_nt(const __nv_bfloat16* __restrict__ Ah, const __nv_bfloat16* __restrict__ Al,
             const __nv_bfloat16* __restrict__ Bh, const __nv_bfloat16* __restrict__ Bl,
             float* __restrict__ C, int K, int lda, int ldb, int ldc,
             long sA, long sB, long sC)
{
    extern __shared__ unsigned su[];

    const int bz = blockIdx.z;
    Ah += (long)bz * sA; Al += (long)bz * sA;
    Bh += (long)bz * sB; Bl += (long)bz * sB;
    C  += (long)bz * sC;

    const int tid  = threadIdx.x;
    const int lane = tid & 31;
    const int wid  = tid >> 5;
    const int wm   = (wid & 3) * 32;
    const int wn   = (wid >> 2) * 32;
    const int m0   = blockIdx.y * 128;
    const int n0   = blockIdx.x * 128;

    const unsigned smemU = (unsigned)__cvta_generic_to_shared(su);

    // cp.async mapping: 4 threads/row, each 2 x 16B chunks (8 bf16) per tile
    const int crow = tid >> 2;                // 0..127
    const int cc   = (tid & 3) * 8;           // element col 0,8,16,24
    const unsigned dsto = (unsigned)(crow * 144 + cc * 2);

    auto stageCopy = [&](int buf, int kt) {
        const unsigned base = smemU + (unsigned)buf * GSTAGE_B;
        const long ao = (long)(m0 + crow) * lda + kt * 64 + cc;
        const long bo = (long)(n0 + crow) * ldb + kt * 64 + cc;
        cp16(base + 0 * GTILE_B + dsto,      Ah + ao);
        cp16(base + 0 * GTILE_B + dsto + 64, Ah + ao + 32);
        cp16(base + 1 * GTILE_B + dsto,      Bh + bo);
        cp16(base + 1 * GTILE_B + dsto + 64, Bh + bo + 32);
        cp16(base + 2 * GTILE_B + dsto,      Al + ao);
        cp16(base + 2 * GTILE_B + dsto + 64, Al + ao + 32);
        cp16(base + 3 * GTILE_B + dsto,      Bl + bo);
        cp16(base + 3 * GTILE_B + dsto + 64, Bl + bo + 32);
    };

    float acc[2][4][4];
#pragma unroll
    for (int i = 0; i < 2; i++)
#pragma unroll
        for (int j = 0; j < 4; j++)
#pragma unroll
            for (int r = 0; r < 4; r++) acc[i][j][r] = 0.f;

    const int r8 = lane & 7;
    const int hb = (lane >> 3) & 1;
    const int hf = lane >> 4;
    unsigned aOff[2], bOff[2];
#pragma unroll
    for (int mi = 0; mi < 2; mi++)
        aOff[mi] = ((wm + mi * 16 + r8 + hb * 8) * 72 + hf * 8) * 2;
#pragma unroll
    for (int p = 0; p < 2; p++)
        bOff[p] = ((wn + p * 16 + r8 + hf * 8) * 72) * 2 + hb * 16;

    const int niter = K >> 6;

    stageCopy(0, 0);
    asm volatile("cp.async.commit_group;");

    for (int it = 0; it < niter; it++) {
        if (it + 1 < niter) {
            stageCopy((it + 1) & 1, it + 1);
            asm volatile("cp.async.commit_group;");
            asm volatile("cp.async.wait_group 1;");
        } else {
            asm volatile("cp.async.wait_group 0;");
        }
        __syncthreads();

        const unsigned stB = smemU + (unsigned)((it & 1) * GSTAGE_B);
        const unsigned aH = stB;
        const unsigned bH = stB + GTILE_B;
        const unsigned aL = stB + 2u * GTILE_B;
        const unsigned bL = stB + 3u * GTILE_B;

#pragma unroll
        for (int ks = 0; ks < 4; ks++) {
            unsigned aFh[2][4], aFl[2][4];
            unsigned bFh[4][2], bFl[4][2];
#pragma unroll
            for (int mi = 0; mi < 2; mi++) {
                asm volatile("ldmatrix.sync.aligned.m8n8.x4.shared.b16 {%0,%1,%2,%3}, [%4];"
                    : "=r"(aFh[mi][0]), "=r"(aFh[mi][1]), "=r"(aFh[mi][2]), "=r"(aFh[mi][3])
                    : "r"(aH + aOff[mi] + ks * 32));
                asm volatile("ldmatrix.sync.aligned.m8n8.x4.shared.b16 {%0,%1,%2,%3}, [%4];"
                    : "=r"(aFl[mi][0]), "=r"(aFl[mi][1]), "=r"(aFl[mi][2]), "=r"(aFl[mi][3])
                    : "r"(aL + aOff[mi] + ks * 32));
            }
#pragma unroll
            for (int p = 0; p < 2; p++) {
                unsigned q0, q1, q2, q3;
                asm volatile("ldmatrix.sync.aligned.m8n8.x4.shared.b16 {%0,%1,%2,%3}, [%4];"
                    : "=r"(q0), "=r"(q1), "=r"(q2), "=r"(q3)
                    : "r"(bH + bOff[p] + ks * 32));
                bFh[2 * p][0] = q0; bFh[2 * p][1] = q1;
                bFh[2 * p + 1][0] = q2; bFh[2 * p + 1][1] = q3;
                asm volatile("ldmatrix.sync.aligned.m8n8.x4.shared.b16 {%0,%1,%2,%3}, [%4];"
                    : "=r"(q0), "=r"(q1), "=r"(q2), "=r"(q3)
                    : "r"(bL + bOff[p] + ks * 32));
                bFl[2 * p][0] = q0; bFl[2 * p][1] = q1;
                bFl[2 * p + 1][0] = q2; bFl[2 * p + 1][1] = q3;
            }
#pragma unroll
            for (int mi = 0; mi < 2; mi++)
#pragma unroll
                for (int nj = 0; nj < 4; nj++) {
                    MMABF(aFh, bFl, mi, nj);
                    MMABF(aFl, bFh, mi, nj);
                    MMABF(aFh, bFh, mi, nj);
                }
        }
        __syncthreads();
    }

    // epilogue: fp32 out
    const int g = lane >> 2;
    const int t = lane & 3;
#pragma unroll
    for (int nj = 0; nj < 4; nj++) {
        const int col = n0 + wn + nj * 8 + t * 2;
#pragma unroll
        for (int mi = 0; mi < 2; mi++) {
            const int row = m0 + wm + mi * 16 + g;
            *reinterpret_cast<float2*>(&C[(long)row * ldc + col]) =
                make_float2(acc[mi][nj][0], acc[mi][nj][1]);
            *reinterpret_cast<float2*>(&C[(long)(row + 8) * ldc + col]) =
                make_float2(acc[mi][nj][2], acc[mi][nj][3]);
        }
    }
}

// ---------------------------------------------------------------------------
// Row softmax: read fp32 scores, write split-bf16 attn. 256 thr / 4096 cols.
// ---------------------------------------------------------------------------
__global__ void __launch_bounds__(256)
softmax_split(const float* __restrict__ S,
              __nv_bfloat16* __restrict__ Ph, __nv_bfloat16* __restrict__ Pl)
{
    const long row = blockIdx.x;
    const float* p = S + row * (long)SEQ;
    const int tid  = threadIdx.x;
    const int lane = tid & 31;
    const int wid  = tid >> 5;

    float vals[16];
    float m = -3.0e38f;
#pragma unroll
    for (int i = 0; i < 4; i++) {
        float4 v = reinterpret_cast<const float4*>(p)[tid + i * 256];
        vals[i * 4 + 0] = v.x; vals[i * 4 + 1] = v.y;
        vals[i * 4 + 2] = v.z; vals[i * 4 + 3] = v.w;
        m = fmaxf(m, fmaxf(fmaxf(v.x, v.y), fmaxf(v.z, v.w)));
    }

    __shared__ float red[8];
#pragma unroll
    for (int off = 16; off > 0; off >>= 1)
        m = fmaxf(m, __shfl_xor_sync(0xffffffffu, m, off));
    if (lane == 0) red[wid] = m;
    __syncthreads();
    float mAll = red[0];
#pragma unroll
    for (int w = 1; w < 8; w++) mAll = fmaxf(mAll, red[w]);
    __syncthreads();

    float s = 0.f;
#pragma unroll
    for (int i = 0; i < 16; i++) {
        vals[i] = __expf(vals[i] - mAll);
        s += vals[i];
    }
#pragma unroll
    for (int off = 16; off > 0; off >>= 1)
        s += __shfl_xor_sync(0xffffffffu, s, off);
    if (lane == 0) red[wid] = s;
    __syncthreads();
    float sAll = 0.f;
#pragma unroll
    for (int w = 0; w < 8; w++) sAll += red[w];
    const float inv = 1.0f / sAll;

    uint2* ph = reinterpret_cast<uint2*>(Ph + row * (long)SEQ);
    uint2* pl = reinterpret_cast<uint2*>(Pl + row * (long)SEQ);
#pragma unroll
    for (int i = 0; i < 4; i++) {
        unsigned h0, h1, l0, l1;
        split2(vals[i * 4 + 0] * inv, vals[i * 4 + 1] * inv, h0, l0);
        split2(vals[i * 4 + 2] * inv, vals[i * 4 + 3] * inv, h1, l1);
        ph[tid + i * 256] = make_uint2(h0, h1);
        pl[tid + i * 256] = make_uint2(l0, l1);
    }
}

// ---------------------------------------------------------------------------
extern "C" void kernel_launch(void* const* d_in, const int* in_sizes, int n_in,
                              void* d_out, int out_size)
{
    const float* q_in = (const float*)d_in[0];
    const float* k_in = (const float*)d_in[1];
    const float* v_in = (const float*)d_in[2];
    const float* Wq   = (const float*)d_in[3];
    const float* bq   = (const float*)d_in[4];
    const float* Wk   = (const float*)d_in[5];
    const float* bk   = (const float*)d_in[6];
    const float* Wv   = (const float*)d_in[7];
    const float* bv   = (const float*)d_in[8];
    float* out = (float*)d_out;

    float* gs;
    __nv_bfloat16 *qh, *ql, *kh, *kl, *vth, *vtl, *ph, *pl;
    cudaGetSymbolAddress((void**)&gs,  g_s);
    cudaGetSymbolAddress((void**)&qh,  g_qh);  cudaGetSymbolAddress((void**)&ql, g_ql);
    cudaGetSymbolAddress((void**)&kh,  g_kh);  cudaGetSymbolAddress((void**)&kl, g_kl);
    cudaGetSymbolAddress((void**)&vth, g_vth); cudaGetSymbolAddress((void**)&vtl, g_vtl);
    cudaGetSymbolAddress((void**)&ph,  g_ph);  cudaGetSymbolAddress((void**)&pl, g_pl);

    static bool attrDone = false;
    if (!attrDone) {
        cudaFuncSetAttribute(proj_gemm<false>,
                             cudaFuncAttributeMaxDynamicSharedMemorySize, PSMEM);
        cudaFuncSetAttribute(proj_gemm<true>,
                             cudaFuncAttributeMaxDynamicSharedMemorySize, PSMEM);
        cudaFuncSetAttribute(gemm_bf16_nt,
                             cudaFuncAttributeMaxDynamicSharedMemorySize, GSMEM);
        attrDone = true;
    }

    dim3 blk(512);

    // 1) projections -> split bf16 (V transposed)
    {
        dim3 grd(EMB / 128, (BATCH * SEQ) / 128, 1);
        proj_gemm<false><<<grd, blk, PSMEM>>>(q_in, Wq, bq, qh, ql, EMB, EMB, EMB, EMB);
        proj_gemm<false><<<grd, blk, PSMEM>>>(k_in, Wk, bk, kh, kl, EMB, EMB, EMB, EMB);
        proj_gemm<true><<<grd, blk, PSMEM>>>(v_in, Wv, bv, vth, vtl, EMB, EMB, EMB, SEQ);
    }

    // 2) scores[b] = q[b] @ k[b]^T  (pre-split bf16 in, fp32 out)
    {
        dim3 grd(SEQ / 128, SEQ / 128, BATCH);
        gemm_bf16_nt<<<grd, blk, GSMEM>>>(qh, ql, kh, kl, gs, EMB, EMB, EMB, SEQ,
                                          (long)SEQ * EMB, (long)SEQ * EMB,
                                          (long)SEQ * SEQ);
    }

    // 3) softmax -> split bf16 attn
    softmax_split<<<BATCH * SEQ, 256>>>(gs, ph, pl);

    // 4) out[b] = attn[b] @ v[b]
    {
        dim3 grd(EMB / 128, SEQ / 128, BATCH);
        gemm_bf16_nt<<<grd, blk, GSMEM>>>(ph, pl, vth, vtl, out, SEQ, SEQ, SEQ, EMB,
                                          (long)SEQ * SEQ, (long)EMB * SEQ,
                                          (long)SEQ * EMB);
    }
}